// round 15
// baseline (speedup 1.0000x reference)
#include <cuda_runtime.h>
#include <math.h>

#define NQ    12
#define DIM   4096
#define KS    6
#define BATCH 256
#define SEQ   128
#define DEMB  512
#define NCLS  8

#define SMEM_BYTES (2 * DIM * 8)   // dynamic: double-buffered state only

// swizzle: XOR low nibble with next nibble (GF(2)-linear)
__device__ __host__ constexpr int swzc(int i) { return i ^ ((i >> 4) & 0xF); }

// CNOT-ring composition: bits 0..10 = suffix parity, bit 11 = parity(bits 0..10)
__device__ __host__ constexpr int permTc(int x) {
    int p = x ^ (x >> 1);
    p ^= p >> 2;
    p ^= p >> 4;
    p ^= p >> 8;
    return (p & 0x7FF) | (((p ^ (x >> 11)) & 1) << 11);
}

__device__ __forceinline__ float2 cmul(float2 a, float2 b) {
    return make_float2(a.x * b.x - a.y * b.y, a.x * b.y + a.y * b.x);
}

// ---- packed f32x2 helpers (issue compression; throughput-neutral on sm_103a) ----
union F2U { float2 f; unsigned long long u; };
__device__ __forceinline__ float2 ffma2(float2 a, float2 b, float2 c) {
    F2U A, B, C, R; A.f = a; B.f = b; C.f = c;
    asm("fma.rn.f32x2 %0, %1, %2, %3;" : "=l"(R.u) : "l"(A.u), "l"(B.u), "l"(C.u));
    return R.f;
}
__device__ __forceinline__ float2 fmul2(float2 a, float2 b) {
    F2U A, B, R; A.f = a; B.f = b;
    asm("mul.rn.f32x2 %0, %1, %2;" : "=l"(R.u) : "l"(A.u), "l"(B.u));
    return R.f;
}

// Scatter (optional) + Z-readout partials, FIRST 2 exchange levels only.
// The serial 3-level shuffle tail + wred store are deferred (finish_reduce)
// to overlap with the next sweep's LDS latency. Caller must __syncthreads()
// after this (orders scatter stores vs next sweep-A loads).
template <bool STORE>
__device__ __forceinline__ void scatter_partial(
    float2 v[16], float2* dst, int t, float u3[3])
{
    const int ybase = permTc(t << 4);          // once per thread
    const int sybase = swzc(ybase);            // swizzled scatter base

    float acc0 = 0.f, acc1 = 0.f, acc2 = 0.f, acc3 = 0.f, acc11 = 0.f, ptot = 0.f;
#pragma unroll
    for (int g = 0; g < 16; g++) {
        const int PT = permTc(g);              // compile-time
        const int SPT = swzc(PT);              // compile-time
        if (STORE) dst[sybase ^ SPT] = v[g];
        float p = v[g].x * v[g].x + v[g].y * v[g].y;
        ptot += p;
        acc0  += (PT & 1)        ? -p : p;
        acc1  += ((PT >> 1) & 1) ? -p : p;
        acc2  += ((PT >> 2) & 1) ? -p : p;
        acc3  += ((PT >> 3) & 1) ? -p : p;
        acc11 += ((PT >> 11) & 1)? -p : p;
    }

    float zb[NQ];
    zb[0]  = (ybase & 1)         ? -acc0  : acc0;
    zb[1]  = ((ybase >> 1) & 1)  ? -acc1  : acc1;
    zb[2]  = ((ybase >> 2) & 1)  ? -acc2  : acc2;
    zb[3]  = ((ybase >> 3) & 1)  ? -acc3  : acc3;
    zb[11] = ((ybase >> 11) & 1) ? -acc11 : acc11;
#pragma unroll
    for (int bb = 4; bb < 11; bb++)
        zb[bb] = ((ybase >> bb) & 1) ? -ptot : ptot;

    // split-exchange: 12 -> 6 -> 3 values
    const int lane = t & 31;
    const bool hi16 = (lane & 16) != 0;
    const bool hi8  = (lane & 8) != 0;
    float s6[6];
#pragma unroll
    for (int j = 0; j < 6; j++) {
        float snd = hi16 ? zb[j] : zb[j + 6];
        float kp  = hi16 ? zb[j + 6] : zb[j];
        s6[j] = kp + __shfl_xor_sync(0xffffffffu, snd, 16);
    }
#pragma unroll
    for (int j = 0; j < 3; j++) {
        float snd = hi8 ? s6[j] : s6[j + 3];
        float kp  = hi8 ? s6[j + 3] : s6[j];
        u3[j] = kp + __shfl_xor_sync(0xffffffffu, snd, 8);
    }
}

// Deferred reduction tail: 3 serial shuffle levels + per-warp partial store.
// wredk = &wredAll[k][0][0]; no barrier needed after (epilogue sync covers).
__device__ __forceinline__ void finish_reduce(float u3[3], float* wredk, int t)
{
#pragma unroll
    for (int j = 0; j < 3; j++) {
        u3[j] += __shfl_xor_sync(0xffffffffu, u3[j], 4);
        u3[j] += __shfl_xor_sync(0xffffffffu, u3[j], 2);
        u3[j] += __shfl_xor_sync(0xffffffffu, u3[j], 1);
    }
    int lane = t & 31, w = t >> 5;
    if ((lane & 7) == 0) {
        int base = (lane >> 3) * 3;
#pragma unroll
        for (int j = 0; j < 3; j++) wredk[w * NQ + base + j] = u3[j];
    }
}

// ---------------------------------------------------------------------------
// Fully fused, 1 sample per CTA, 256 threads, grid=256 (2 CTAs/SM).
// D*R*D decomposition with ALL diagonals commuted out of the butterflies:
// sweeps A/B/C are pure-real rotations; diagonals applied via 16-entry
// tables (group bits) and XOR-split tables (thread bits). Readout reduction
// tail deferred past the inter-step barrier.
// ---------------------------------------------------------------------------
__global__ void __launch_bounds__(256, 2) fused_kernel(
    const int* __restrict__ ids, const int* __restrict__ mask,
    const float* __restrict__ emb, const float* __restrict__ pw,
    const float* __restrict__ pb, const float* __restrict__ theta,
    const float* __restrict__ hw, const float* __restrict__ hb,
    float* __restrict__ out)
{
    extern __shared__ float2 st[];              // [2][DIM] dynamic
    __shared__ float2 gp[KS][NQ][4];            // [0]=(c,s) [1]=wpre [2]=wpost [3]=s*wpost
    __shared__ float2 gbc[KS][NQ];              // packed (c,c)
    __shared__ float2 gbs[KS][NQ];              // packed (s,s)
    __shared__ float2 gbn[KS][NQ];              // packed (-s,-s)
    __shared__ float2 plo[16], pt1[16], pt2[16];
    __shared__ float2 dpre1[KS][16], dpre2[KS][16];  // wpre: wires 11..8 / 7..4 (thread bits)
    __shared__ float2 dpo1[KS][16],  dpo2[KS][16];   // wpost: wires 7..4 / 3..0 (thread bits)
    __shared__ float2 dA16[KS][16];             // wpre wires 3..0 (sweep-A group bits)
    __shared__ float2 dC16[KS][16];             // wpost wires 11..8 (sweep-C group bits)
    __shared__ float  wredAll[KS][8][NQ];       // per-step per-warp partials
    __shared__ float  xs[NQ];

    int b = blockIdx.x, t = threadIdx.x;

    // ===================== encoder phase (scratch aliases st) ================
    {
        int*   sid  = (int*)st;                  // [SEQ]
        float* smk  = (float*)st + SEQ;          // [SEQ]
        float* ered = (float*)st + 2 * SEQ;      // [8][13]
        if (t < SEQ) {
            sid[t] = ids[b * SEQ + t];
            smk[t] = (float)mask[b * SEQ + t];
        }
        __syncthreads();

        int d = t & 127, sh = t >> 7;            // dim-chunk, seq-half
        float a0 = 0.f, a1 = 0.f, a2 = 0.f, a3 = 0.f, cnt = 0.f;
#pragma unroll 4
        for (int s = sh * 64; s < sh * 64 + 64; s++) {
            float m = smk[s];
            cnt += m;
            const float4 e = __ldg((const float4*)(emb + (size_t)sid[s] * DEMB + d * 4));
            a0 += m * e.x; a1 += m * e.y; a2 += m * e.z; a3 += m * e.w;
        }

        float z[NQ];
#pragma unroll
        for (int q = 0; q < NQ; q++) {
            const float4 w = __ldg((const float4*)(pw + q * DEMB + d * 4));
            z[q] = a0 * w.x + a1 * w.y + a2 * w.z + a3 * w.w;
        }
        const int lane = t & 31;
        const bool hi16 = (lane & 16) != 0;
        const bool hi8  = (lane & 8) != 0;
        float s6[6];
#pragma unroll
        for (int j = 0; j < 6; j++) {
            float snd = hi16 ? z[j] : z[j + 6];
            float kp  = hi16 ? z[j + 6] : z[j];
            s6[j] = kp + __shfl_xor_sync(0xffffffffu, snd, 16);
        }
        float u3[3];
#pragma unroll
        for (int j = 0; j < 3; j++) {
            float snd = hi8 ? s6[j] : s6[j + 3];
            float kp  = hi8 ? s6[j + 3] : s6[j];
            u3[j] = kp + __shfl_xor_sync(0xffffffffu, snd, 8);
        }
#pragma unroll
        for (int j = 0; j < 3; j++) {
            u3[j] += __shfl_xor_sync(0xffffffffu, u3[j], 4);
            u3[j] += __shfl_xor_sync(0xffffffffu, u3[j], 2);
            u3[j] += __shfl_xor_sync(0xffffffffu, u3[j], 1);
        }
#pragma unroll
        for (int off = 16; off; off >>= 1)
            cnt += __shfl_down_sync(0xffffffffu, cnt, off);

        __syncthreads();                         // sid/smk reads complete
        int w = t >> 5;
        if ((lane & 7) == 0) {
            int base = (lane >> 3) * 3;
#pragma unroll
            for (int j = 0; j < 3; j++) ered[w * 13 + base + j] = u3[j];
        }
        if (lane == 0) ered[w * 13 + NQ] = cnt;
        __syncthreads();
        if (t < NQ) {
            float s = 0.f, c = 0.f;
#pragma unroll
            for (int w2 = 0; w2 < 8; w2++) { s += ered[w2 * 13 + t]; c += ered[w2 * 13 + NQ]; }
            float inv = 1.0f / fmaxf(c * (1.0f / 128.0f), 1.0f);
            xs[t] = tanhf(s * inv + pb[t]) * 3.14159265358979f;
        }
        __syncthreads();
    }

    // ===================== gate precompute (D*R*D), 72 threads ===============
    if (t < KS * NQ) {
        int k = t / NQ, q = t % NQ;
        float cy, sy;  sincosf(0.5f * xs[q], &sy, &cy);
        const float* th = theta + (k * NQ + q) * 3;
        float phi = th[0], tha = th[1], om = th[2];
        float ct, stt; sincosf(0.5f * tha, &stt, &ct);
        float ca, sa;  sincosf(0.5f * (phi + om), &sa, &ca); // ep = (ca,-sa)
        float cb, sb;  sincosf(0.5f * (phi - om), &sb, &cb); // em = (cb, sb)
        float r00 = ct * cy, r01 = ct * sy, r10 = stt * cy, r11 = stt * sy;
        float2 G00 = make_float2( ca * r00 - cb * r11, -sa * r00 - sb * r11);
        float2 G01 = make_float2(-ca * r01 - cb * r10,  sa * r01 - sb * r10);
        float2 G10 = make_float2( cb * r10 + ca * r01, -sb * r10 + sa * r01);

        float c = sqrtf(G00.x * G00.x + G00.y * G00.y);
        float s = sqrtf(G10.x * G10.x + G10.y * G10.y);
        float2 cj = make_float2(G00.x, -G00.y);
        float2 wpre = cmul(make_float2(-G01.x, -G01.y), cj);
        float n1 = wpre.x * wpre.x + wpre.y * wpre.y;
        if (n1 > 1e-24f) { float r = rsqrtf(n1); wpre.x *= r; wpre.y *= r; }
        else wpre = make_float2(1.f, 0.f);
        float2 wpost = cmul(G10, cj);
        float n2 = wpost.x * wpost.x + wpost.y * wpost.y;
        if (n2 > 1e-24f) { float r = rsqrtf(n2); wpost.x *= r; wpost.y *= r; }
        else wpost = make_float2(1.f, 0.f);

        gp[k][q][0] = make_float2(c, s);
        gp[k][q][1] = wpre;
        gp[k][q][2] = wpost;
        gp[k][q][3] = make_float2(s * wpost.x, s * wpost.y);  // col0 bit-1 entry
        gbc[k][q] = make_float2(c, c);
        gbs[k][q] = make_float2(s, s);
        gbn[k][q] = make_float2(-s, -s);
    }
    __syncthreads();

    // step-1 tables (col0 = (c, s*wpost) products):
    if (t < 48) {
        int half = t >> 4, m = t & 15;
        int w0 = (half == 0) ? 11 : (half == 1) ? 7 : 3;
        float2 p = make_float2(1.f, 0.f);
#pragma unroll
        for (int j = 0; j < 4; j++) {
            float2 f = ((m >> j) & 1) ? gp[0][w0 - j][3]
                                      : make_float2(gp[0][w0 - j][0].x, 0.f);
            p = cmul(p, f);
        }
        float2* dst = (half == 0) ? plo : (half == 1) ? pt1 : pt2;
        dst[m] = p;
    }
    // diag tables for steps 1..5: 6 tables x 16 entries x 5 steps = 480
    {
        int idx = t;
#pragma unroll
        for (int pass = 0; pass < 2; pass++, idx += 256) {
            if (idx < (KS - 1) * 96) {
                int k = 1 + idx / 96, r = idx % 96, tbl = r >> 4, m = r & 15;
                int w0  = (tbl == 0 || tbl == 5) ? 11 : (tbl == 3 || tbl == 4) ? 3 : 7;
                int col = (tbl <= 1 || tbl == 4) ? 1 : 2;
                float2 e = make_float2(1.f, 0.f);
#pragma unroll
                for (int j = 0; j < 4; j++)
                    if ((m >> j) & 1) e = cmul(e, gp[k][w0 - j][col]);
                float2* dst = (tbl == 0) ? dpre1[k] : (tbl == 1) ? dpre2[k]
                            : (tbl == 2) ? dpo1[k]  : (tbl == 3) ? dpo2[k]
                            : (tbl == 4) ? dA16[k]  : dC16[k];
                dst[m] = e;
            }
        }
    }
    __syncthreads();

    float u3c[3];   // carried readout partials (deferred reduction)

    // ===== step 1 (analytic product state): amp = pt1[t&15]*pt2[t>>4]*plo[g]
    {
        float2 pt = cmul(pt1[t & 15], pt2[(t >> 4) & 15]);
        float2 v[16];
#pragma unroll
        for (int g = 0; g < 16; g++) v[g] = cmul(pt, plo[g]);
        scatter_partial<true>(v, st, t, u3c);    // -> buf0
        __syncthreads();
    }

    // per-thread swizzled bases (step-invariant)
    const int swzA  = swzc(t);                       // sweep A: + (g<<8)
    const int baseB = (t & 15) | ((t >> 4) << 8);    // sweep B: ^ ((g<<4)|g)
    const int swzC  = (t << 4) | (t & 15);           // sweep C: ^ g
    const int tlo = t & 15, thi = (t >> 4) & 15;

    // ===== steps 2..6 =====
    for (int k = 1; k < KS; k++) {
        float2* src = st + (((k + 1) & 1) ? DIM : 0);
        float2* dst = st + ((k & 1) ? DIM : 0);
        float2 v[16];

        // --- sweep A loads (issue first; shuffle tail overlaps LDS latency) ---
#pragma unroll
        for (int g = 0; g < 16; g++) v[g] = src[swzA + (g << 8)];

        // deferred reduction tail of step k-1
        finish_reduce(u3c, &wredAll[k - 1][0][0], t);

        // --- sweep A: pre-diag on group bits, then 4 real levels (wires 3..0)
#pragma unroll
        for (int g = 0; g < 16; g++) v[g] = cmul(dA16[k][g], v[g]);
#pragma unroll
        for (int k2 = 0; k2 < 4; k2++) {
            int w = 3 - k2;
            float2 c2 = gbc[k][w], s2 = gbs[k][w], n2 = gbn[k][w];
            int sft = 1 << k2;
#pragma unroll
            for (int i = 0; i < 16; i++) {
                if (i & sft) continue;
                float2 p0 = v[i], p1 = v[i | sft];
                v[i]       = ffma2(n2, p1, fmul2(c2, p0));
                v[i | sft] = ffma2(c2, p1, fmul2(s2, p0));
            }
        }
        // pre-diag fixed bits (wires 11..4) at store
        {
            float2 dfx = cmul(dpre1[k][tlo], dpre2[k][thi]);
#pragma unroll
            for (int g = 0; g < 16; g++) src[swzA + (g << 8)] = cmul(dfx, v[g]);
        }
        __syncthreads();

        // --- sweep B: 4 real levels (wires 7..4) ---
#pragma unroll
        for (int g = 0; g < 16; g++) v[g] = src[baseB ^ ((g << 4) | g)];
#pragma unroll
        for (int k2 = 0; k2 < 4; k2++) {
            int w = 7 - k2;
            float2 c2 = gbc[k][w], s2 = gbs[k][w], n2 = gbn[k][w];
            int sft = 1 << k2;
#pragma unroll
            for (int i = 0; i < 16; i++) {
                if (i & sft) continue;
                float2 p0 = v[i], p1 = v[i | sft];
                v[i]       = ffma2(n2, p1, fmul2(c2, p0));
                v[i | sft] = ffma2(c2, p1, fmul2(s2, p0));
            }
        }
#pragma unroll
        for (int g = 0; g < 16; g++) src[baseB ^ ((g << 4) | g)] = v[g];
        __syncthreads();

        // --- sweep C: 4 real levels (wires 11..8), then combined post-diag ---
#pragma unroll
        for (int g = 0; g < 16; g++) v[g] = src[swzC ^ g];
#pragma unroll
        for (int k2 = 0; k2 < 4; k2++) {
            int w = 11 - k2;
            float2 c2 = gbc[k][w], s2 = gbs[k][w], n2 = gbn[k][w];
            int sft = 1 << k2;
#pragma unroll
            for (int i = 0; i < 16; i++) {
                if (i & sft) continue;
                float2 p0 = v[i], p1 = v[i | sft];
                v[i]       = ffma2(n2, p1, fmul2(c2, p0));
                v[i | sft] = ffma2(c2, p1, fmul2(s2, p0));
            }
        }

        if (k < KS - 1) {
            // post-diag: dfp (thread bits, wires 7..0) x dC16 (group bits, 11..8)
            float2 dfp = cmul(dpo1[k][tlo], dpo2[k][thi]);
#pragma unroll
            for (int g = 0; g < 16; g++) v[g] = cmul(dfp, cmul(dC16[k][g], v[g]));
            scatter_partial<true>(v, dst, t, u3c);
        } else {
            // last step: post-diag & scatter skipped (only |amp|^2 needed)
            scatter_partial<false>(v, dst, t, u3c);
        }
        __syncthreads();
    }
    finish_reduce(u3c, &wredAll[KS - 1][0][0], t);
    __syncthreads();

    // epilogue: cross-warp readout sums + heads.
    // Layout: step_logits[6,256,8] | step_readouts[6,256,12] | final[256,8]
    if (t < KS * NCLS) {
        int k = t >> 3, c = t & 7;
        float s = hb[c];
#pragma unroll
        for (int j = 0; j < NQ; j++) {
            float r = 0.f;
#pragma unroll
            for (int w2 = 0; w2 < 8; w2++) r += wredAll[k][w2][11 - j];
            s += hw[c * NQ + j] * r;
        }
        out[(k * BATCH + b) * NCLS + c] = s;
        if (k == KS - 1)
            out[KS * BATCH * NCLS + KS * BATCH * NQ + b * NCLS + c] = s;
    }
    if (t >= 64 && t < 64 + KS * NQ) {
        int u = t - 64;
        int k = u / NQ, j = u % NQ;
        float r = 0.f;
#pragma unroll
        for (int w2 = 0; w2 < 8; w2++) r += wredAll[k][w2][11 - j];
        out[KS * BATCH * NCLS + (k * BATCH + b) * NQ + j] = r;
    }
}

extern "C" void kernel_launch(void* const* d_in, const int* in_sizes, int n_in,
                              void* d_out, int out_size)
{
    const int*   ids   = (const int*)d_in[0];
    const int*   mask  = (const int*)d_in[1];
    const float* emb   = (const float*)d_in[2];
    const float* pw    = (const float*)d_in[3];
    const float* pb    = (const float*)d_in[4];
    const float* theta = (const float*)d_in[5];
    const float* hw    = (const float*)d_in[6];
    const float* hb    = (const float*)d_in[7];
    float* out = (float*)d_out;

    cudaFuncSetAttribute(fused_kernel,
                         cudaFuncAttributeMaxDynamicSharedMemorySize, SMEM_BYTES);
    fused_kernel<<<BATCH, 256, SMEM_BYTES>>>(ids, mask, emb, pw, pb,
                                             theta, hw, hb, out);
}

// round 16
// speedup vs baseline: 1.0077x; 1.0077x over previous
#include <cuda_runtime.h>
#include <math.h>

#define NQ    12
#define DIM   4096
#define KS    6
#define BATCH 256
#define SEQ   128
#define DEMB  512
#define NCLS  8

#define SMEM_BYTES (2 * DIM * 8)   // dynamic: double-buffered state only

// swizzle: XOR low nibble with next nibble (GF(2)-linear)
__device__ __host__ constexpr int swzc(int i) { return i ^ ((i >> 4) & 0xF); }

// CNOT-ring composition: bits 0..10 = suffix parity, bit 11 = parity(bits 0..10)
__device__ __host__ constexpr int permTc(int x) {
    int p = x ^ (x >> 1);
    p ^= p >> 2;
    p ^= p >> 4;
    p ^= p >> 8;
    return (p & 0x7FF) | (((p ^ (x >> 11)) & 1) << 11);
}

__device__ __forceinline__ float2 cmul(float2 a, float2 b) {
    return make_float2(a.x * b.x - a.y * b.y, a.x * b.y + a.y * b.x);
}

// ---- packed f32x2 helpers (issue compression; throughput-neutral on sm_103a) ----
union F2U { float2 f; unsigned long long u; };
__device__ __forceinline__ float2 ffma2(float2 a, float2 b, float2 c) {
    F2U A, B, C, R; A.f = a; B.f = b; C.f = c;
    asm("fma.rn.f32x2 %0, %1, %2, %3;" : "=l"(R.u) : "l"(A.u), "l"(B.u), "l"(C.u));
    return R.f;
}
__device__ __forceinline__ float2 fmul2(float2 a, float2 b) {
    F2U A, B, R; A.f = a; B.f = b;
    asm("mul.rn.f32x2 %0, %1, %2;" : "=l"(R.u) : "l"(A.u), "l"(B.u));
    return R.f;
}

// Scatter (optional) + Z-readout partials, FIRST 2 exchange levels only.
// The serial 3-level shuffle tail + wred store are deferred (finish_reduce)
// to overlap with the next sweep's LDS latency. Caller must __syncthreads()
// after this (orders scatter stores vs next sweep-A loads).
template <bool STORE>
__device__ __forceinline__ void scatter_partial(
    float2 v[16], float2* dst, int t, float u3[3])
{
    const int ybase = permTc(t << 4);          // once per thread
    const int sybase = swzc(ybase);            // swizzled scatter base

    float acc0 = 0.f, acc1 = 0.f, acc2 = 0.f, acc3 = 0.f, acc11 = 0.f, ptot = 0.f;
#pragma unroll
    for (int g = 0; g < 16; g++) {
        const int PT = permTc(g);              // compile-time
        const int SPT = swzc(PT);              // compile-time
        if (STORE) dst[sybase ^ SPT] = v[g];
        float p = v[g].x * v[g].x + v[g].y * v[g].y;
        ptot += p;
        acc0  += (PT & 1)        ? -p : p;
        acc1  += ((PT >> 1) & 1) ? -p : p;
        acc2  += ((PT >> 2) & 1) ? -p : p;
        acc3  += ((PT >> 3) & 1) ? -p : p;
        acc11 += ((PT >> 11) & 1)? -p : p;
    }

    float zb[NQ];
    zb[0]  = (ybase & 1)         ? -acc0  : acc0;
    zb[1]  = ((ybase >> 1) & 1)  ? -acc1  : acc1;
    zb[2]  = ((ybase >> 2) & 1)  ? -acc2  : acc2;
    zb[3]  = ((ybase >> 3) & 1)  ? -acc3  : acc3;
    zb[11] = ((ybase >> 11) & 1) ? -acc11 : acc11;
#pragma unroll
    for (int bb = 4; bb < 11; bb++)
        zb[bb] = ((ybase >> bb) & 1) ? -ptot : ptot;

    // split-exchange: 12 -> 6 -> 3 values
    const int lane = t & 31;
    const bool hi16 = (lane & 16) != 0;
    const bool hi8  = (lane & 8) != 0;
    float s6[6];
#pragma unroll
    for (int j = 0; j < 6; j++) {
        float snd = hi16 ? zb[j] : zb[j + 6];
        float kp  = hi16 ? zb[j + 6] : zb[j];
        s6[j] = kp + __shfl_xor_sync(0xffffffffu, snd, 16);
    }
#pragma unroll
    for (int j = 0; j < 3; j++) {
        float snd = hi8 ? s6[j] : s6[j + 3];
        float kp  = hi8 ? s6[j + 3] : s6[j];
        u3[j] = kp + __shfl_xor_sync(0xffffffffu, snd, 8);
    }
}

// Deferred reduction tail: 3 serial shuffle levels + per-warp partial store.
// wredk = &wredAll[k][0][0]; no barrier needed after (epilogue sync covers).
__device__ __forceinline__ void finish_reduce(float u3[3], float* wredk, int t)
{
#pragma unroll
    for (int j = 0; j < 3; j++) {
        u3[j] += __shfl_xor_sync(0xffffffffu, u3[j], 4);
        u3[j] += __shfl_xor_sync(0xffffffffu, u3[j], 2);
        u3[j] += __shfl_xor_sync(0xffffffffu, u3[j], 1);
    }
    int lane = t & 31, w = t >> 5;
    if ((lane & 7) == 0) {
        int base = (lane >> 3) * 3;
#pragma unroll
        for (int j = 0; j < 3; j++) wredk[w * NQ + base + j] = u3[j];
    }
}

// ---------------------------------------------------------------------------
// Fully fused, 1 sample per CTA, 256 threads, grid=256 (2 CTAs/SM).
// All diagonals commuted out of the butterflies (pure-real rotation sweeps);
// B->C exchange is intra-warp (producers of C-thread t's amps are threads
// (t&~15)..(t|15)) -> __syncwarp instead of __syncthreads. 2 full barriers
// + 1 warp barrier per step. Readout reduction tail deferred.
// ---------------------------------------------------------------------------
__global__ void __launch_bounds__(256, 2) fused_kernel(
    const int* __restrict__ ids, const int* __restrict__ mask,
    const float* __restrict__ emb, const float* __restrict__ pw,
    const float* __restrict__ pb, const float* __restrict__ theta,
    const float* __restrict__ hw, const float* __restrict__ hb,
    float* __restrict__ out)
{
    extern __shared__ float2 st[];              // [2][DIM] dynamic
    __shared__ float2 gp[KS][NQ][4];            // [0]=(c,s) [1]=wpre [2]=wpost [3]=s*wpost
    __shared__ float2 gbc[KS][NQ];              // packed (c,c)
    __shared__ float2 gbs[KS][NQ];              // packed (s,s)
    __shared__ float2 gbn[KS][NQ];              // packed (-s,-s)
    __shared__ float2 plo[16], pt1[16], pt2[16];
    __shared__ float2 dpre1[KS][16], dpre2[KS][16];  // wpre: wires 11..8 / 7..4 (thread bits)
    __shared__ float2 dpo1[KS][16],  dpo2[KS][16];   // wpost: wires 7..4 / 3..0 (thread bits)
    __shared__ float2 dA16[KS][16];             // wpre wires 3..0 (sweep-A group bits)
    __shared__ float2 dC16[KS][16];             // wpost wires 11..8 (sweep-C group bits)
    __shared__ float  wredAll[KS][8][NQ];       // per-step per-warp partials
    __shared__ float  xs[NQ];

    int b = blockIdx.x, t = threadIdx.x;

    // ===================== encoder phase (scratch aliases st) ================
    {
        int*   sid  = (int*)st;                  // [SEQ]
        float* smk  = (float*)st + SEQ;          // [SEQ]
        float* ered = (float*)st + 2 * SEQ;      // [8][13]
        if (t < SEQ) {
            sid[t] = ids[b * SEQ + t];
            smk[t] = (float)mask[b * SEQ + t];
        }
        __syncthreads();

        int d = t & 127, sh = t >> 7;            // dim-chunk, seq-half
        float a0 = 0.f, a1 = 0.f, a2 = 0.f, a3 = 0.f, cnt = 0.f;
#pragma unroll 4
        for (int s = sh * 64; s < sh * 64 + 64; s++) {
            float m = smk[s];
            cnt += m;
            const float4 e = __ldg((const float4*)(emb + (size_t)sid[s] * DEMB + d * 4));
            a0 += m * e.x; a1 += m * e.y; a2 += m * e.z; a3 += m * e.w;
        }

        float z[NQ];
#pragma unroll
        for (int q = 0; q < NQ; q++) {
            const float4 w = __ldg((const float4*)(pw + q * DEMB + d * 4));
            z[q] = a0 * w.x + a1 * w.y + a2 * w.z + a3 * w.w;
        }
        const int lane = t & 31;
        const bool hi16 = (lane & 16) != 0;
        const bool hi8  = (lane & 8) != 0;
        float s6[6];
#pragma unroll
        for (int j = 0; j < 6; j++) {
            float snd = hi16 ? z[j] : z[j + 6];
            float kp  = hi16 ? z[j + 6] : z[j];
            s6[j] = kp + __shfl_xor_sync(0xffffffffu, snd, 16);
        }
        float u3[3];
#pragma unroll
        for (int j = 0; j < 3; j++) {
            float snd = hi8 ? s6[j] : s6[j + 3];
            float kp  = hi8 ? s6[j + 3] : s6[j];
            u3[j] = kp + __shfl_xor_sync(0xffffffffu, snd, 8);
        }
#pragma unroll
        for (int j = 0; j < 3; j++) {
            u3[j] += __shfl_xor_sync(0xffffffffu, u3[j], 4);
            u3[j] += __shfl_xor_sync(0xffffffffu, u3[j], 2);
            u3[j] += __shfl_xor_sync(0xffffffffu, u3[j], 1);
        }
#pragma unroll
        for (int off = 16; off; off >>= 1)
            cnt += __shfl_down_sync(0xffffffffu, cnt, off);

        __syncthreads();                         // sid/smk reads complete
        int w = t >> 5;
        if ((lane & 7) == 0) {
            int base = (lane >> 3) * 3;
#pragma unroll
            for (int j = 0; j < 3; j++) ered[w * 13 + base + j] = u3[j];
        }
        if (lane == 0) ered[w * 13 + NQ] = cnt;
        __syncthreads();
        if (t < NQ) {
            float s = 0.f, c = 0.f;
#pragma unroll
            for (int w2 = 0; w2 < 8; w2++) { s += ered[w2 * 13 + t]; c += ered[w2 * 13 + NQ]; }
            float inv = 1.0f / fmaxf(c * (1.0f / 128.0f), 1.0f);
            xs[t] = tanhf(s * inv + pb[t]) * 3.14159265358979f;
        }
        __syncthreads();
    }

    // ===================== gate precompute (D*R*D), 72 threads ===============
    if (t < KS * NQ) {
        int k = t / NQ, q = t % NQ;
        float cy, sy;  sincosf(0.5f * xs[q], &sy, &cy);
        const float* th = theta + (k * NQ + q) * 3;
        float phi = th[0], tha = th[1], om = th[2];
        float ct, stt; sincosf(0.5f * tha, &stt, &ct);
        float ca, sa;  sincosf(0.5f * (phi + om), &sa, &ca); // ep = (ca,-sa)
        float cb, sb;  sincosf(0.5f * (phi - om), &sb, &cb); // em = (cb, sb)
        float r00 = ct * cy, r01 = ct * sy, r10 = stt * cy, r11 = stt * sy;
        float2 G00 = make_float2( ca * r00 - cb * r11, -sa * r00 - sb * r11);
        float2 G01 = make_float2(-ca * r01 - cb * r10,  sa * r01 - sb * r10);
        float2 G10 = make_float2( cb * r10 + ca * r01, -sb * r10 + sa * r01);

        float c = sqrtf(G00.x * G00.x + G00.y * G00.y);
        float s = sqrtf(G10.x * G10.x + G10.y * G10.y);
        float2 cj = make_float2(G00.x, -G00.y);
        float2 wpre = cmul(make_float2(-G01.x, -G01.y), cj);
        float n1 = wpre.x * wpre.x + wpre.y * wpre.y;
        if (n1 > 1e-24f) { float r = rsqrtf(n1); wpre.x *= r; wpre.y *= r; }
        else wpre = make_float2(1.f, 0.f);
        float2 wpost = cmul(G10, cj);
        float n2 = wpost.x * wpost.x + wpost.y * wpost.y;
        if (n2 > 1e-24f) { float r = rsqrtf(n2); wpost.x *= r; wpost.y *= r; }
        else wpost = make_float2(1.f, 0.f);

        gp[k][q][0] = make_float2(c, s);
        gp[k][q][1] = wpre;
        gp[k][q][2] = wpost;
        gp[k][q][3] = make_float2(s * wpost.x, s * wpost.y);  // col0 bit-1 entry
        gbc[k][q] = make_float2(c, c);
        gbs[k][q] = make_float2(s, s);
        gbn[k][q] = make_float2(-s, -s);
    }
    __syncthreads();

    // step-1 tables (col0 = (c, s*wpost) products):
    if (t < 48) {
        int half = t >> 4, m = t & 15;
        int w0 = (half == 0) ? 11 : (half == 1) ? 7 : 3;
        float2 p = make_float2(1.f, 0.f);
#pragma unroll
        for (int j = 0; j < 4; j++) {
            float2 f = ((m >> j) & 1) ? gp[0][w0 - j][3]
                                      : make_float2(gp[0][w0 - j][0].x, 0.f);
            p = cmul(p, f);
        }
        float2* dst = (half == 0) ? plo : (half == 1) ? pt1 : pt2;
        dst[m] = p;
    }
    // diag tables for steps 1..5: 6 tables x 16 entries x 5 steps = 480
    {
        int idx = t;
#pragma unroll
        for (int pass = 0; pass < 2; pass++, idx += 256) {
            if (idx < (KS - 1) * 96) {
                int k = 1 + idx / 96, r = idx % 96, tbl = r >> 4, m = r & 15;
                int w0  = (tbl == 0 || tbl == 5) ? 11 : (tbl == 3 || tbl == 4) ? 3 : 7;
                int col = (tbl <= 1 || tbl == 4) ? 1 : 2;
                float2 e = make_float2(1.f, 0.f);
#pragma unroll
                for (int j = 0; j < 4; j++)
                    if ((m >> j) & 1) e = cmul(e, gp[k][w0 - j][col]);
                float2* dst = (tbl == 0) ? dpre1[k] : (tbl == 1) ? dpre2[k]
                            : (tbl == 2) ? dpo1[k]  : (tbl == 3) ? dpo2[k]
                            : (tbl == 4) ? dA16[k]  : dC16[k];
                dst[m] = e;
            }
        }
    }
    __syncthreads();

    float u3c[3];   // carried readout partials (deferred reduction)

    // ===== step 1 (analytic product state): amp = pt1[t&15]*pt2[t>>4]*plo[g]
    {
        float2 pt = cmul(pt1[t & 15], pt2[(t >> 4) & 15]);
        float2 v[16];
#pragma unroll
        for (int g = 0; g < 16; g++) v[g] = cmul(pt, plo[g]);
        scatter_partial<true>(v, st, t, u3c);    // -> buf0
        __syncthreads();
    }

    // per-thread swizzled bases (step-invariant)
    const int swzA  = swzc(t);                       // sweep A: + (g<<8)
    const int baseB = (t & 15) | ((t >> 4) << 8);    // sweep B: ^ ((g<<4)|g)
    const int swzC  = (t << 4) | (t & 15);           // sweep C: ^ g
    const int tlo = t & 15, thi = (t >> 4) & 15;

    // ===== steps 2..6 =====
    for (int k = 1; k < KS; k++) {
        float2* src = st + (((k + 1) & 1) ? DIM : 0);
        float2* dst = st + ((k & 1) ? DIM : 0);
        float2 v[16];

        // --- sweep A loads (issue first; shuffle tail overlaps LDS latency) ---
#pragma unroll
        for (int g = 0; g < 16; g++) v[g] = src[swzA + (g << 8)];

        // deferred reduction tail of step k-1
        finish_reduce(u3c, &wredAll[k - 1][0][0], t);

        // --- sweep A: pre-diag on group bits, then 4 real levels (wires 3..0)
#pragma unroll
        for (int g = 0; g < 16; g++) v[g] = cmul(dA16[k][g], v[g]);
#pragma unroll
        for (int k2 = 0; k2 < 4; k2++) {
            int w = 3 - k2;
            float2 c2 = gbc[k][w], s2 = gbs[k][w], n2 = gbn[k][w];
            int sft = 1 << k2;
#pragma unroll
            for (int i = 0; i < 16; i++) {
                if (i & sft) continue;
                float2 p0 = v[i], p1 = v[i | sft];
                v[i]       = ffma2(n2, p1, fmul2(c2, p0));
                v[i | sft] = ffma2(c2, p1, fmul2(s2, p0));
            }
        }
        // pre-diag fixed bits (wires 11..4) at store
        {
            float2 dfx = cmul(dpre1[k][tlo], dpre2[k][thi]);
#pragma unroll
            for (int g = 0; g < 16; g++) src[swzA + (g << 8)] = cmul(dfx, v[g]);
        }
        __syncthreads();     // A->B exchange spans warps (producers stride-16)

        // --- sweep B: 4 real levels (wires 7..4) ---
#pragma unroll
        for (int g = 0; g < 16; g++) v[g] = src[baseB ^ ((g << 4) | g)];
#pragma unroll
        for (int k2 = 0; k2 < 4; k2++) {
            int w = 7 - k2;
            float2 c2 = gbc[k][w], s2 = gbs[k][w], n2 = gbn[k][w];
            int sft = 1 << k2;
#pragma unroll
            for (int i = 0; i < 16; i++) {
                if (i & sft) continue;
                float2 p0 = v[i], p1 = v[i | sft];
                v[i]       = ffma2(n2, p1, fmul2(c2, p0));
                v[i | sft] = ffma2(c2, p1, fmul2(s2, p0));
            }
        }
#pragma unroll
        for (int g = 0; g < 16; g++) src[baseB ^ ((g << 4) | g)] = v[g];
        // B->C exchange is INTRA-WARP: C-thread t's 16 amps were written by
        // B-threads ((t>>4)<<4)|g, all within t's own 16-aligned block (same
        // warp). Warp-scope sync suffices.
        __syncwarp();

        // --- sweep C: 4 real levels (wires 11..8), then combined post-diag ---
#pragma unroll
        for (int g = 0; g < 16; g++) v[g] = src[swzC ^ g];
#pragma unroll
        for (int k2 = 0; k2 < 4; k2++) {
            int w = 11 - k2;
            float2 c2 = gbc[k][w], s2 = gbs[k][w], n2 = gbn[k][w];
            int sft = 1 << k2;
#pragma unroll
            for (int i = 0; i < 16; i++) {
                if (i & sft) continue;
                float2 p0 = v[i], p1 = v[i | sft];
                v[i]       = ffma2(n2, p1, fmul2(c2, p0));
                v[i | sft] = ffma2(c2, p1, fmul2(s2, p0));
            }
        }

        if (k < KS - 1) {
            // post-diag: dfp (thread bits, wires 7..0) x dC16 (group bits, 11..8)
            float2 dfp = cmul(dpo1[k][tlo], dpo2[k][thi]);
#pragma unroll
            for (int g = 0; g < 16; g++) v[g] = cmul(dfp, cmul(dC16[k][g], v[g]));
            scatter_partial<true>(v, dst, t, u3c);
        } else {
            // last step: post-diag & scatter skipped (only |amp|^2 needed)
            scatter_partial<false>(v, dst, t, u3c);
        }
        __syncthreads();     // scatter -> next sweep-A exchange spans warps
    }
    finish_reduce(u3c, &wredAll[KS - 1][0][0], t);
    __syncthreads();

    // epilogue: cross-warp readout sums + heads.
    // Layout: step_logits[6,256,8] | step_readouts[6,256,12] | final[256,8]
    if (t < KS * NCLS) {
        int k = t >> 3, c = t & 7;
        float s = hb[c];
#pragma unroll
        for (int j = 0; j < NQ; j++) {
            float r = 0.f;
#pragma unroll
            for (int w2 = 0; w2 < 8; w2++) r += wredAll[k][w2][11 - j];
            s += hw[c * NQ + j] * r;
        }
        out[(k * BATCH + b) * NCLS + c] = s;
        if (k == KS - 1)
            out[KS * BATCH * NCLS + KS * BATCH * NQ + b * NCLS + c] = s;
    }
    if (t >= 64 && t < 64 + KS * NQ) {
        int u = t - 64;
        int k = u / NQ, j = u % NQ;
        float r = 0.f;
#pragma unroll
        for (int w2 = 0; w2 < 8; w2++) r += wredAll[k][w2][11 - j];
        out[KS * BATCH * NCLS + (k * BATCH + b) * NQ + j] = r;
    }
}

extern "C" void kernel_launch(void* const* d_in, const int* in_sizes, int n_in,
                              void* d_out, int out_size)
{
    const int*   ids   = (const int*)d_in[0];
    const int*   mask  = (const int*)d_in[1];
    const float* emb   = (const float*)d_in[2];
    const float* pw    = (const float*)d_in[3];
    const float* pb    = (const float*)d_in[4];
    const float* theta = (const float*)d_in[5];
    const float* hw    = (const float*)d_in[6];
    const float* hb    = (const float*)d_in[7];
    float* out = (float*)d_out;

    cudaFuncSetAttribute(fused_kernel,
                         cudaFuncAttributeMaxDynamicSharedMemorySize, SMEM_BYTES);
    fused_kernel<<<BATCH, 256, SMEM_BYTES>>>(ids, mask, emb, pw, pb,
                                             theta, hw, hb, out);
}

// round 17
// speedup vs baseline: 1.0366x; 1.0287x over previous
#include <cuda_runtime.h>
#include <math.h>

#define NQ    12
#define DIM   4096
#define KS    6
#define BATCH 256
#define SEQ   128
#define DEMB  512
#define NCLS  8

#define SMEM_BYTES (2 * DIM * 8)   // dynamic: double-buffered state only

// swizzle: XOR low nibble with next nibble (GF(2)-linear)
__device__ __host__ constexpr int swzc(int i) { return i ^ ((i >> 4) & 0xF); }

// CNOT-ring composition: bits 0..10 = suffix parity, bit 11 = parity(bits 0..10)
__device__ __host__ constexpr int permTc(int x) {
    int p = x ^ (x >> 1);
    p ^= p >> 2;
    p ^= p >> 4;
    p ^= p >> 8;
    return (p & 0x7FF) | (((p ^ (x >> 11)) & 1) << 11);
}

__device__ __forceinline__ float2 cmul(float2 a, float2 b) {
    return make_float2(a.x * b.x - a.y * b.y, a.x * b.y + a.y * b.x);
}

// ---- packed f32x2 helpers (issue compression; throughput-neutral on sm_103a) ----
union F2U { float2 f; unsigned long long u; };
__device__ __forceinline__ float2 ffma2(float2 a, float2 b, float2 c) {
    F2U A, B, C, R; A.f = a; B.f = b; C.f = c;
    asm("fma.rn.f32x2 %0, %1, %2, %3;" : "=l"(R.u) : "l"(A.u), "l"(B.u), "l"(C.u));
    return R.f;
}
__device__ __forceinline__ float2 fmul2(float2 a, float2 b) {
    F2U A, B, R; A.f = a; B.f = b;
    asm("mul.rn.f32x2 %0, %1, %2;" : "=l"(R.u) : "l"(A.u), "l"(B.u));
    return R.f;
}

// Scatter (optional) + Z-readout partials, FIRST 2 exchange levels only.
// The serial 3-level shuffle tail + wred store are deferred (finish_reduce)
// to overlap with the next sweep's LDS latency. Caller must __syncthreads()
// after this (orders scatter stores vs next sweep-A loads).
template <bool STORE>
__device__ __forceinline__ void scatter_partial(
    float2 v[16], float2* dst, int t, float u3[3])
{
    const int ybase = permTc(t << 4);          // once per thread
    const int sybase = swzc(ybase);            // swizzled scatter base

    float acc0 = 0.f, acc1 = 0.f, acc2 = 0.f, acc3 = 0.f, acc11 = 0.f, ptot = 0.f;
#pragma unroll
    for (int g = 0; g < 16; g++) {
        const int PT = permTc(g);              // compile-time
        const int SPT = swzc(PT);              // compile-time
        if (STORE) dst[sybase ^ SPT] = v[g];
        float p = v[g].x * v[g].x + v[g].y * v[g].y;
        ptot += p;
        acc0  += (PT & 1)        ? -p : p;
        acc1  += ((PT >> 1) & 1) ? -p : p;
        acc2  += ((PT >> 2) & 1) ? -p : p;
        acc3  += ((PT >> 3) & 1) ? -p : p;
        acc11 += ((PT >> 11) & 1)? -p : p;
    }

    float zb[NQ];
    zb[0]  = (ybase & 1)         ? -acc0  : acc0;
    zb[1]  = ((ybase >> 1) & 1)  ? -acc1  : acc1;
    zb[2]  = ((ybase >> 2) & 1)  ? -acc2  : acc2;
    zb[3]  = ((ybase >> 3) & 1)  ? -acc3  : acc3;
    zb[11] = ((ybase >> 11) & 1) ? -acc11 : acc11;
#pragma unroll
    for (int bb = 4; bb < 11; bb++)
        zb[bb] = ((ybase >> bb) & 1) ? -ptot : ptot;

    // split-exchange: 12 -> 6 -> 3 values
    const int lane = t & 31;
    const bool hi16 = (lane & 16) != 0;
    const bool hi8  = (lane & 8) != 0;
    float s6[6];
#pragma unroll
    for (int j = 0; j < 6; j++) {
        float snd = hi16 ? zb[j] : zb[j + 6];
        float kp  = hi16 ? zb[j + 6] : zb[j];
        s6[j] = kp + __shfl_xor_sync(0xffffffffu, snd, 16);
    }
#pragma unroll
    for (int j = 0; j < 3; j++) {
        float snd = hi8 ? s6[j] : s6[j + 3];
        float kp  = hi8 ? s6[j + 3] : s6[j];
        u3[j] = kp + __shfl_xor_sync(0xffffffffu, snd, 8);
    }
}

// Deferred reduction tail: 3 serial shuffle levels + per-warp partial store.
// wredk = &wredAll[k][0][0]; no barrier needed after (epilogue sync covers).
__device__ __forceinline__ void finish_reduce(float u3[3], float* wredk, int t)
{
#pragma unroll
    for (int j = 0; j < 3; j++) {
        u3[j] += __shfl_xor_sync(0xffffffffu, u3[j], 4);
        u3[j] += __shfl_xor_sync(0xffffffffu, u3[j], 2);
        u3[j] += __shfl_xor_sync(0xffffffffu, u3[j], 1);
    }
    int lane = t & 31, w = t >> 5;
    if ((lane & 7) == 0) {
        int base = (lane >> 3) * 3;
#pragma unroll
        for (int j = 0; j < 3; j++) wredk[w * NQ + base + j] = u3[j];
    }
}

// ---------------------------------------------------------------------------
// Fully fused, 1 sample per CTA, 256 threads, grid=256 (2 CTAs/SM).
// All diagonals commuted out of the butterflies (pure-real rotation sweeps);
// B->C exchange is intra-warp (producers of C-thread t's amps are threads
// (t&~15)..(t|15)) -> __syncwarp instead of __syncthreads. 2 full barriers
// + 1 warp barrier per step. Readout reduction tail deferred.
// ---------------------------------------------------------------------------
__global__ void __launch_bounds__(256, 2) fused_kernel(
    const int* __restrict__ ids, const int* __restrict__ mask,
    const float* __restrict__ emb, const float* __restrict__ pw,
    const float* __restrict__ pb, const float* __restrict__ theta,
    const float* __restrict__ hw, const float* __restrict__ hb,
    float* __restrict__ out)
{
    extern __shared__ float2 st[];              // [2][DIM] dynamic
    __shared__ float2 gp[KS][NQ][4];            // [0]=(c,s) [1]=wpre [2]=wpost [3]=s*wpost
    __shared__ float2 gbc[KS][NQ];              // packed (c,c)
    __shared__ float2 gbs[KS][NQ];              // packed (s,s)
    __shared__ float2 gbn[KS][NQ];              // packed (-s,-s)
    __shared__ float2 plo[16], pt1[16], pt2[16];
    __shared__ float2 dpre1[KS][16], dpre2[KS][16];  // wpre: wires 11..8 / 7..4 (thread bits)
    __shared__ float2 dpo1[KS][16],  dpo2[KS][16];   // wpost: wires 7..4 / 3..0 (thread bits)
    __shared__ float2 dA16[KS][16];             // wpre wires 3..0 (sweep-A group bits)
    __shared__ float2 dC16[KS][16];             // wpost wires 11..8 (sweep-C group bits)
    __shared__ float  wredAll[KS][8][NQ];       // per-step per-warp partials
    __shared__ float  xs[NQ];

    int b = blockIdx.x, t = threadIdx.x;

    // ===================== encoder phase (scratch aliases st) ================
    {
        int*   sid  = (int*)st;                  // [SEQ]
        float* smk  = (float*)st + SEQ;          // [SEQ]
        float* ered = (float*)st + 2 * SEQ;      // [8][13]
        if (t < SEQ) {
            sid[t] = ids[b * SEQ + t];
            smk[t] = (float)mask[b * SEQ + t];
        }
        __syncthreads();

        int d = t & 127, sh = t >> 7;            // dim-chunk, seq-half
        float a0 = 0.f, a1 = 0.f, a2 = 0.f, a3 = 0.f, cnt = 0.f;
#pragma unroll 4
        for (int s = sh * 64; s < sh * 64 + 64; s++) {
            float m = smk[s];
            cnt += m;
            const float4 e = __ldg((const float4*)(emb + (size_t)sid[s] * DEMB + d * 4));
            a0 += m * e.x; a1 += m * e.y; a2 += m * e.z; a3 += m * e.w;
        }

        float z[NQ];
#pragma unroll
        for (int q = 0; q < NQ; q++) {
            const float4 w = __ldg((const float4*)(pw + q * DEMB + d * 4));
            z[q] = a0 * w.x + a1 * w.y + a2 * w.z + a3 * w.w;
        }
        const int lane = t & 31;
        const bool hi16 = (lane & 16) != 0;
        const bool hi8  = (lane & 8) != 0;
        float s6[6];
#pragma unroll
        for (int j = 0; j < 6; j++) {
            float snd = hi16 ? z[j] : z[j + 6];
            float kp  = hi16 ? z[j + 6] : z[j];
            s6[j] = kp + __shfl_xor_sync(0xffffffffu, snd, 16);
        }
        float u3[3];
#pragma unroll
        for (int j = 0; j < 3; j++) {
            float snd = hi8 ? s6[j] : s6[j + 3];
            float kp  = hi8 ? s6[j + 3] : s6[j];
            u3[j] = kp + __shfl_xor_sync(0xffffffffu, snd, 8);
        }
#pragma unroll
        for (int j = 0; j < 3; j++) {
            u3[j] += __shfl_xor_sync(0xffffffffu, u3[j], 4);
            u3[j] += __shfl_xor_sync(0xffffffffu, u3[j], 2);
            u3[j] += __shfl_xor_sync(0xffffffffu, u3[j], 1);
        }
#pragma unroll
        for (int off = 16; off; off >>= 1)
            cnt += __shfl_down_sync(0xffffffffu, cnt, off);

        __syncthreads();                         // sid/smk reads complete
        int w = t >> 5;
        if ((lane & 7) == 0) {
            int base = (lane >> 3) * 3;
#pragma unroll
            for (int j = 0; j < 3; j++) ered[w * 13 + base + j] = u3[j];
        }
        if (lane == 0) ered[w * 13 + NQ] = cnt;
        __syncthreads();
        if (t < NQ) {
            float s = 0.f, c = 0.f;
#pragma unroll
            for (int w2 = 0; w2 < 8; w2++) { s += ered[w2 * 13 + t]; c += ered[w2 * 13 + NQ]; }
            float inv = 1.0f / fmaxf(c * (1.0f / 128.0f), 1.0f);
            xs[t] = tanhf(s * inv + pb[t]) * 3.14159265358979f;
        }
        __syncthreads();
    }

    // ===================== gate precompute (D*R*D), 72 threads ===============
    if (t < KS * NQ) {
        int k = t / NQ, q = t % NQ;
        float cy, sy;  sincosf(0.5f * xs[q], &sy, &cy);
        const float* th = theta + (k * NQ + q) * 3;
        float phi = th[0], tha = th[1], om = th[2];
        float ct, stt; sincosf(0.5f * tha, &stt, &ct);
        float ca, sa;  sincosf(0.5f * (phi + om), &sa, &ca); // ep = (ca,-sa)
        float cb, sb;  sincosf(0.5f * (phi - om), &sb, &cb); // em = (cb, sb)
        float r00 = ct * cy, r01 = ct * sy, r10 = stt * cy, r11 = stt * sy;
        float2 G00 = make_float2( ca * r00 - cb * r11, -sa * r00 - sb * r11);
        float2 G01 = make_float2(-ca * r01 - cb * r10,  sa * r01 - sb * r10);
        float2 G10 = make_float2( cb * r10 + ca * r01, -sb * r10 + sa * r01);

        float c = sqrtf(G00.x * G00.x + G00.y * G00.y);
        float s = sqrtf(G10.x * G10.x + G10.y * G10.y);
        float2 cj = make_float2(G00.x, -G00.y);
        float2 wpre = cmul(make_float2(-G01.x, -G01.y), cj);
        float n1 = wpre.x * wpre.x + wpre.y * wpre.y;
        if (n1 > 1e-24f) { float r = rsqrtf(n1); wpre.x *= r; wpre.y *= r; }
        else wpre = make_float2(1.f, 0.f);
        float2 wpost = cmul(G10, cj);
        float n2 = wpost.x * wpost.x + wpost.y * wpost.y;
        if (n2 > 1e-24f) { float r = rsqrtf(n2); wpost.x *= r; wpost.y *= r; }
        else wpost = make_float2(1.f, 0.f);

        gp[k][q][0] = make_float2(c, s);
        gp[k][q][1] = wpre;
        gp[k][q][2] = wpost;
        gp[k][q][3] = make_float2(s * wpost.x, s * wpost.y);  // col0 bit-1 entry
        gbc[k][q] = make_float2(c, c);
        gbs[k][q] = make_float2(s, s);
        gbn[k][q] = make_float2(-s, -s);
    }
    __syncthreads();

    // step-1 tables (col0 = (c, s*wpost) products):
    if (t < 48) {
        int half = t >> 4, m = t & 15;
        int w0 = (half == 0) ? 11 : (half == 1) ? 7 : 3;
        float2 p = make_float2(1.f, 0.f);
#pragma unroll
        for (int j = 0; j < 4; j++) {
            float2 f = ((m >> j) & 1) ? gp[0][w0 - j][3]
                                      : make_float2(gp[0][w0 - j][0].x, 0.f);
            p = cmul(p, f);
        }
        float2* dst = (half == 0) ? plo : (half == 1) ? pt1 : pt2;
        dst[m] = p;
    }
    // diag tables for steps 1..5: 6 tables x 16 entries x 5 steps = 480
    {
        int idx = t;
#pragma unroll
        for (int pass = 0; pass < 2; pass++, idx += 256) {
            if (idx < (KS - 1) * 96) {
                int k = 1 + idx / 96, r = idx % 96, tbl = r >> 4, m = r & 15;
                int w0  = (tbl == 0 || tbl == 5) ? 11 : (tbl == 3 || tbl == 4) ? 3 : 7;
                int col = (tbl <= 1 || tbl == 4) ? 1 : 2;
                float2 e = make_float2(1.f, 0.f);
#pragma unroll
                for (int j = 0; j < 4; j++)
                    if ((m >> j) & 1) e = cmul(e, gp[k][w0 - j][col]);
                float2* dst = (tbl == 0) ? dpre1[k] : (tbl == 1) ? dpre2[k]
                            : (tbl == 2) ? dpo1[k]  : (tbl == 3) ? dpo2[k]
                            : (tbl == 4) ? dA16[k]  : dC16[k];
                dst[m] = e;
            }
        }
    }
    __syncthreads();

    float u3c[3];   // carried readout partials (deferred reduction)

    // ===== step 1 (analytic product state): amp = pt1[t&15]*pt2[t>>4]*plo[g]
    {
        float2 pt = cmul(pt1[t & 15], pt2[(t >> 4) & 15]);
        float2 v[16];
#pragma unroll
        for (int g = 0; g < 16; g++) v[g] = cmul(pt, plo[g]);
        scatter_partial<true>(v, st, t, u3c);    // -> buf0
        __syncthreads();
    }

    // per-thread swizzled bases (step-invariant)
    const int swzA  = swzc(t);                       // sweep A: + (g<<8)
    const int baseB = (t & 15) | ((t >> 4) << 8);    // sweep B: ^ ((g<<4)|g)
    const int swzC  = (t << 4) | (t & 15);           // sweep C: ^ g
    const int tlo = t & 15, thi = (t >> 4) & 15;

    // ===== steps 2..6 =====
    for (int k = 1; k < KS; k++) {
        float2* src = st + (((k + 1) & 1) ? DIM : 0);
        float2* dst = st + ((k & 1) ? DIM : 0);
        float2 v[16];

        // --- sweep A loads (issue first; shuffle tail overlaps LDS latency) ---
#pragma unroll
        for (int g = 0; g < 16; g++) v[g] = src[swzA + (g << 8)];

        // deferred reduction tail of step k-1
        finish_reduce(u3c, &wredAll[k - 1][0][0], t);

        // --- sweep A: pre-diag on group bits, then 4 real levels (wires 3..0)
#pragma unroll
        for (int g = 0; g < 16; g++) v[g] = cmul(dA16[k][g], v[g]);
#pragma unroll
        for (int k2 = 0; k2 < 4; k2++) {
            int w = 3 - k2;
            float2 c2 = gbc[k][w], s2 = gbs[k][w], n2 = gbn[k][w];
            int sft = 1 << k2;
#pragma unroll
            for (int i = 0; i < 16; i++) {
                if (i & sft) continue;
                float2 p0 = v[i], p1 = v[i | sft];
                v[i]       = ffma2(n2, p1, fmul2(c2, p0));
                v[i | sft] = ffma2(c2, p1, fmul2(s2, p0));
            }
        }
        // pre-diag fixed bits (wires 11..4) at store
        {
            float2 dfx = cmul(dpre1[k][tlo], dpre2[k][thi]);
#pragma unroll
            for (int g = 0; g < 16; g++) src[swzA + (g << 8)] = cmul(dfx, v[g]);
        }
        __syncthreads();     // A->B exchange spans warps (producers stride-16)

        // --- sweep B: 4 real levels (wires 7..4) ---
#pragma unroll
        for (int g = 0; g < 16; g++) v[g] = src[baseB ^ ((g << 4) | g)];
#pragma unroll
        for (int k2 = 0; k2 < 4; k2++) {
            int w = 7 - k2;
            float2 c2 = gbc[k][w], s2 = gbs[k][w], n2 = gbn[k][w];
            int sft = 1 << k2;
#pragma unroll
            for (int i = 0; i < 16; i++) {
                if (i & sft) continue;
                float2 p0 = v[i], p1 = v[i | sft];
                v[i]       = ffma2(n2, p1, fmul2(c2, p0));
                v[i | sft] = ffma2(c2, p1, fmul2(s2, p0));
            }
        }
#pragma unroll
        for (int g = 0; g < 16; g++) src[baseB ^ ((g << 4) | g)] = v[g];
        // B->C exchange is INTRA-WARP: C-thread t's 16 amps were written by
        // B-threads ((t>>4)<<4)|g, all within t's own 16-aligned block (same
        // warp). Warp-scope sync suffices.
        __syncwarp();

        // --- sweep C: 4 real levels (wires 11..8), then combined post-diag ---
#pragma unroll
        for (int g = 0; g < 16; g++) v[g] = src[swzC ^ g];
#pragma unroll
        for (int k2 = 0; k2 < 4; k2++) {
            int w = 11 - k2;
            float2 c2 = gbc[k][w], s2 = gbs[k][w], n2 = gbn[k][w];
            int sft = 1 << k2;
#pragma unroll
            for (int i = 0; i < 16; i++) {
                if (i & sft) continue;
                float2 p0 = v[i], p1 = v[i | sft];
                v[i]       = ffma2(n2, p1, fmul2(c2, p0));
                v[i | sft] = ffma2(c2, p1, fmul2(s2, p0));
            }
        }

        if (k < KS - 1) {
            // post-diag: dfp (thread bits, wires 7..0) x dC16 (group bits, 11..8)
            float2 dfp = cmul(dpo1[k][tlo], dpo2[k][thi]);
#pragma unroll
            for (int g = 0; g < 16; g++) v[g] = cmul(dfp, cmul(dC16[k][g], v[g]));
            scatter_partial<true>(v, dst, t, u3c);
        } else {
            // last step: post-diag & scatter skipped (only |amp|^2 needed)
            scatter_partial<false>(v, dst, t, u3c);
        }
        __syncthreads();     // scatter -> next sweep-A exchange spans warps
    }
    finish_reduce(u3c, &wredAll[KS - 1][0][0], t);
    __syncthreads();

    // epilogue: cross-warp readout sums + heads.
    // Layout: step_logits[6,256,8] | step_readouts[6,256,12] | final[256,8]
    if (t < KS * NCLS) {
        int k = t >> 3, c = t & 7;
        float s = hb[c];
#pragma unroll
        for (int j = 0; j < NQ; j++) {
            float r = 0.f;
#pragma unroll
            for (int w2 = 0; w2 < 8; w2++) r += wredAll[k][w2][11 - j];
            s += hw[c * NQ + j] * r;
        }
        out[(k * BATCH + b) * NCLS + c] = s;
        if (k == KS - 1)
            out[KS * BATCH * NCLS + KS * BATCH * NQ + b * NCLS + c] = s;
    }
    if (t >= 64 && t < 64 + KS * NQ) {
        int u = t - 64;
        int k = u / NQ, j = u % NQ;
        float r = 0.f;
#pragma unroll
        for (int w2 = 0; w2 < 8; w2++) r += wredAll[k][w2][11 - j];
        out[KS * BATCH * NCLS + (k * BATCH + b) * NQ + j] = r;
    }
}

extern "C" void kernel_launch(void* const* d_in, const int* in_sizes, int n_in,
                              void* d_out, int out_size)
{
    const int*   ids   = (const int*)d_in[0];
    const int*   mask  = (const int*)d_in[1];
    const float* emb   = (const float*)d_in[2];
    const float* pw    = (const float*)d_in[3];
    const float* pb    = (const float*)d_in[4];
    const float* theta = (const float*)d_in[5];
    const float* hw    = (const float*)d_in[6];
    const float* hb    = (const float*)d_in[7];
    float* out = (float*)d_out;

    cudaFuncSetAttribute(fused_kernel,
                         cudaFuncAttributeMaxDynamicSharedMemorySize, SMEM_BYTES);
    fused_kernel<<<BATCH, 256, SMEM_BYTES>>>(ids, mask, emb, pw, pb,
                                             theta, hw, hb, out);
}